// round 7
// baseline (speedup 1.0000x reference)
#include <cuda_runtime.h>
#include <cuda_bf16.h>
#include <math.h>
#include <stdint.h>
#include <mma.h>

using namespace nvcuda;

#define D 128
#define MAXN 50000
#define NPAD 50048           // 391 * 128, row-padded: GEMM C stores need no guard
#define LDM 132              // smem leading dim (float4-aligned, 2-way conflicts max)

// ---------------- scratch ----------------
__device__ float g_h[NPAD * D];
__device__ float g_mgh[NPAD * 512];       // [m (128) | gh (384)] fused GEMM output
__device__ float g_agg[NPAD * D];
__device__ float g_gi[NPAD * 3 * D];
__device__ float g_Bcat[2 * 512 * D];     // per layer: [convT (128 rows) ; w_hh (384 rows)]

// ================= wmma tf32 GEMM =================
// C[N x M] = A[N x 128] @ B^T ; B is [M rows, 128 cols] K-major.
// CTA tile 128x64, 256 threads = 8 warps (4m x 2n), warp tile 32x32.
// 2 CTAs/SM (smem 101 KB, regs capped at 128).
#define SMEM_FLOATS ((128 + 64) * LDM)

__global__ __launch_bounds__(256, 2)
void gemm_wmma(const float* __restrict__ A, const float* __restrict__ Bw,
               float* __restrict__ C, int N, int M) {
    extern __shared__ float smem[];
    float* As = smem;               // [128][LDM]
    float* Bs = smem + 128 * LDM;   // [64][LDM], rows = output cols (n)

    int tid = threadIdx.x;
    int w = tid >> 5;
    int block_row = blockIdx.y * 128;
    int block_col = blockIdx.x * 64;

    // ---- stage A tile (fp32 -> tf32), guarded rows ----
    {
        int r = tid >> 1;             // 0..127
        int kb = (tid & 1) * 64;      // 0 or 64
        bool va = (block_row + r) < N;
        const float4* arow = (const float4*)(A + (size_t)(block_row + r) * 128 + kb);
        float4 z4 = make_float4(0.f, 0.f, 0.f, 0.f);
#pragma unroll
        for (int i = 0; i < 16; i++) {
            float4 x = va ? arow[i] : z4;
            x.x = wmma::__float_to_tf32(x.x);
            x.y = wmma::__float_to_tf32(x.y);
            x.z = wmma::__float_to_tf32(x.z);
            x.w = wmma::__float_to_tf32(x.w);
            *(float4*)&As[r * LDM + kb + i * 4] = x;
        }
    }
    // ---- stage B tile (64 rows, always valid) ----
    {
        int r = tid >> 2;             // 0..63
        int kb = (tid & 3) * 32;      // 0,32,64,96
        const float4* brow = (const float4*)(Bw + (size_t)(block_col + r) * 128 + kb);
#pragma unroll
        for (int i = 0; i < 8; i++) {
            float4 y = brow[i];
            y.x = wmma::__float_to_tf32(y.x);
            y.y = wmma::__float_to_tf32(y.y);
            y.z = wmma::__float_to_tf32(y.z);
            y.w = wmma::__float_to_tf32(y.w);
            *(float4*)&Bs[r * LDM + kb + i * 4] = y;
        }
    }
    __syncthreads();

    int wm = w >> 1;   // 0..3
    int wn = w & 1;    // 0..1
    const float* aBase = &As[wm * 32 * LDM];
    const float* bBase = &Bs[wn * 32 * LDM];

    wmma::fragment<wmma::accumulator, 16, 16, 8, float> acc[2][2];
#pragma unroll
    for (int i = 0; i < 2; i++)
#pragma unroll
        for (int j = 0; j < 2; j++)
            wmma::fill_fragment(acc[i][j], 0.0f);

#pragma unroll
    for (int s = 0; s < 16; s++) {
        const int k = s * 8;
        wmma::fragment<wmma::matrix_a, 16, 16, 8, wmma::precision::tf32,
                       wmma::row_major> af[2];
        wmma::fragment<wmma::matrix_b, 16, 16, 8, wmma::precision::tf32,
                       wmma::col_major> bf[2];
#pragma unroll
        for (int i = 0; i < 2; i++)
            wmma::load_matrix_sync(af[i], aBase + (i * 16) * LDM + k, LDM);
#pragma unroll
        for (int j = 0; j < 2; j++)
            wmma::load_matrix_sync(bf[j], bBase + (j * 16) * LDM + k, LDM);
#pragma unroll
        for (int i = 0; i < 2; i++)
#pragma unroll
            for (int j = 0; j < 2; j++)
                wmma::mma_sync(acc[i][j], af[i], bf[j], acc[i][j]);
    }

    // ---- direct store (C row-padded; no guard) ----
    float* cw = C + (size_t)(block_row + wm * 32) * M + block_col + wn * 32;
#pragma unroll
    for (int i = 0; i < 2; i++)
#pragma unroll
        for (int j = 0; j < 2; j++)
            wmma::store_matrix_sync(cw + (size_t)(i * 16) * M + j * 16, acc[i][j],
                                    M, wmma::mem_row_major);
}

// ---------------- build B_cat[l] = [convT(128 rows) ; w_hh(384 rows)] ----------------
__global__ void prep_kernel(const float* __restrict__ conv_w,
                            const float* __restrict__ w_hh,
                            float* __restrict__ Bcat) {
    int idx = blockIdx.x * blockDim.x + threadIdx.x;
    if (idx >= 2 * 512 * D) return;
    int l = idx / (512 * D);
    int rem = idx % (512 * D);
    int n = rem / D;
    int k = rem % D;
    float v;
    if (n < 128) v = conv_w[(size_t)l * D * D + (size_t)k * D + n];  // transpose
    else         v = w_hh[(size_t)(n - 128) * D + k];
    Bcat[idx] = v;
}

// ---------------- gather: h = embed[node_ids]; also zero agg ----------------
__global__ void gather_kernel(const int* __restrict__ node_ids,
                              const float4* __restrict__ embed4,
                              float4* __restrict__ h4,
                              float4* __restrict__ agg4, int N) {
    int idx = blockIdx.x * blockDim.x + threadIdx.x;
    if (idx >= N * 32) return;
    int n = idx >> 5;
    int c = idx & 31;
    int id = node_ids[n];
    h4[(size_t)n * 32 + c] = embed4[(size_t)id * 32 + c];
    agg4[idx] = make_float4(0.f, 0.f, 0.f, 0.f);
}

// ---------------- edge scatter: agg[dst] += mgh[src][0:128], one warp per edge ----------------
__global__ void scatter_kernel(const float4* __restrict__ mgh4,
                               const int* __restrict__ src,
                               const int* __restrict__ dst,
                               float* __restrict__ agg, int E) {
    int e = blockIdx.x * (blockDim.x >> 5) + (threadIdx.x >> 5);
    int lane = threadIdx.x & 31;
    if (e >= E) return;
    int s = __ldg(&src[e]);
    int d = __ldg(&dst[e]);
    float4 v = mgh4[(size_t)s * 128 + lane];   // row stride 512 floats, cols 0..127
    float* p = agg + (size_t)d * D + lane * 4;
    asm volatile("red.global.add.v4.f32 [%0], {%1, %2, %3, %4};"
                 :: "l"(p), "f"(v.x), "f"(v.y), "f"(v.z), "f"(v.w) : "memory");
}

// ---------------- GRU gate fusion; gh read from mgh (offset 128, stride 512) ----------------
__global__ void gru_kernel(const float4* __restrict__ gi4,
                           const float4* __restrict__ mgh4,
                           const float4* __restrict__ bih4,
                           const float4* __restrict__ bhh4,
                           float4* __restrict__ h4,
                           float4* __restrict__ agg4,
                           int total4, int zero_agg) {
    int idx = blockIdx.x * blockDim.x + threadIdx.x;
    if (idx >= total4) return;
    int n = idx >> 5;
    int c = idx & 31;
    const float4* gin = gi4 + (size_t)n * 96;
    const float4* ghn = mgh4 + (size_t)n * 128 + 32;   // skip 128 floats of m
    float4 ir = gin[c], iz = gin[c + 32], in_ = gin[c + 64];
    float4 hr = ghn[c], hz = ghn[c + 32], hn = ghn[c + 64];
    float4 bir = bih4[c], biz = bih4[c + 32], bin = bih4[c + 64];
    float4 bhr = bhh4[c], bhz = bhh4[c + 32], bhn = bhh4[c + 64];
    float4 h = h4[idx];
    float4 o;
#define GRU1(X)                                                                 \
    {                                                                           \
        float r = 1.0f / (1.0f + __expf(-(ir.X + bir.X + hr.X + bhr.X)));       \
        float z = 1.0f / (1.0f + __expf(-(iz.X + biz.X + hz.X + bhz.X)));       \
        float nn = tanhf(in_.X + bin.X + r * (hn.X + bhn.X));                   \
        o.X = (1.0f - z) * nn + z * h.X;                                        \
    }
    GRU1(x) GRU1(y) GRU1(z) GRU1(w)
#undef GRU1
    h4[idx] = o;
    if (zero_agg) agg4[idx] = make_float4(0.f, 0.f, 0.f, 0.f);
}

// ---------------- per-graph mean pool (batch sorted) ----------------
__device__ __forceinline__ int lower_bound_dev(const int* a, int n, int key) {
    int lo = 0, hi = n;
    while (lo < hi) {
        int mid = (lo + hi) >> 1;
        if (a[mid] < key) lo = mid + 1; else hi = mid;
    }
    return lo;
}

__global__ void pool_kernel(const float* __restrict__ h,
                            const int* __restrict__ batch,
                            float* __restrict__ out, int N) {
    int g = blockIdx.x;
    int tid = threadIdx.x;
    int sub = tid >> 7;
    int d = tid & 127;
    __shared__ int s_lo, s_hi;
    __shared__ float sbuf[4][128];
    if (tid == 0) {
        s_lo = lower_bound_dev(batch, N, g);
        s_hi = lower_bound_dev(batch, N, g + 1);
    }
    __syncthreads();
    int lo = s_lo, hi = s_hi;
    float acc = 0.0f;
    for (int n = lo + sub; n < hi; n += 4)
        acc += h[(size_t)n * D + d];
    sbuf[sub][d] = acc;
    __syncthreads();
    if (sub == 0) {
        float total = sbuf[0][d] + sbuf[1][d] + sbuf[2][d] + sbuf[3][d];
        float cnt = (float)(hi - lo);
        out[(size_t)g * D + d] = total / fmaxf(cnt, 1.0f);
    }
}

// ---------------- launch ----------------
extern "C" void kernel_launch(void* const* d_in, const int* in_sizes, int n_in,
                              void* d_out, int out_size) {
    const int* node_ids = (const int*)d_in[0];
    const int* edge_index = (const int*)d_in[1];
    const int* batch = (const int*)d_in[2];
    const float* embed = (const float*)d_in[4];
    const float* conv_w = (const float*)d_in[5];
    const float* w_ih = (const float*)d_in[6];
    const float* w_hh = (const float*)d_in[7];
    const float* b_ih = (const float*)d_in[8];
    const float* b_hh = (const float*)d_in[9];
    float* out = (float*)d_out;

    int N = in_sizes[0];
    int E = in_sizes[1] / 2;
    int G = out_size / D;
    const int* src = edge_index;
    const int* dst = edge_index + E;

    float *h, *mgh, *agg, *gi, *Bcat;
    cudaGetSymbolAddress((void**)&h, g_h);
    cudaGetSymbolAddress((void**)&mgh, g_mgh);
    cudaGetSymbolAddress((void**)&agg, g_agg);
    cudaGetSymbolAddress((void**)&gi, g_gi);
    cudaGetSymbolAddress((void**)&Bcat, g_Bcat);

    static int smem_set = 0;
    if (!smem_set) {
        cudaFuncSetAttribute(gemm_wmma, cudaFuncAttributeMaxDynamicSharedMemorySize,
                             SMEM_FLOATS * (int)sizeof(float));
        smem_set = 1;
    }

    prep_kernel<<<(2 * 512 * D + 255) / 256, 256>>>(conv_w, w_hh, Bcat);
    gather_kernel<<<(N * 32 + 255) / 256, 256>>>(node_ids, (const float4*)embed,
                                                 (float4*)h, (float4*)agg, N);

    int rowBlocks = (N + 127) / 128;   // 391
    size_t smemBytes = SMEM_FLOATS * sizeof(float);

    for (int layer = 0; layer < 2; layer++) {
        // [m | gh] = h @ [convT ; w_hh]^T  (one staging of h, M=512)
        gemm_wmma<<<dim3(512 / 64, rowBlocks), 256, smemBytes>>>(
            h, Bcat + (size_t)layer * 512 * D, mgh, N, 512);

        // agg[dst] += m[src]
        {
            int warpsPerBlock = 8;
            int blocks = (E + warpsPerBlock - 1) / warpsPerBlock;
            scatter_kernel<<<blocks, warpsPerBlock * 32>>>((const float4*)mgh, src, dst,
                                                           agg, E);
        }

        // gi = agg @ w_ih^T
        gemm_wmma<<<dim3(384 / 64, rowBlocks), 256, smemBytes>>>(agg, w_ih, gi, N, 384);

        // h = GRU(gi, gh, h); zero agg for next layer's scatter
        gru_kernel<<<(N * 32 + 255) / 256, 256>>>((const float4*)gi,
                                                  (const float4*)mgh,
                                                  (const float4*)b_ih,
                                                  (const float4*)b_hh,
                                                  (float4*)h, (float4*)agg,
                                                  N * 32, layer == 0 ? 1 : 0);
    }

    pool_kernel<<<G, 512>>>(h, batch, out, N);
}

// round 8
// speedup vs baseline: 1.1788x; 1.1788x over previous
#include <cuda_runtime.h>
#include <cuda_bf16.h>
#include <math.h>
#include <stdint.h>

#define D 128
#define MAXN 50000

// ---------------- scratch ----------------
__device__ float g_h[MAXN * D];
__device__ float g_m[MAXN * D];
__device__ float g_agg[MAXN * D];
__device__ float g_gi[MAXN * 3 * D];
__device__ float g_gh[MAXN * 3 * D];
__device__ float g_wihT[D * 3 * D];   // [K=128][M=384]
__device__ float g_whhT[D * 3 * D];

// ---------------- weight transpose: WT[k][m] = W[m][k], W is [384,128] ----------------
__global__ void transpose_kernel(const float* __restrict__ W, float* __restrict__ WT) {
    int idx = blockIdx.x * blockDim.x + threadIdx.x;
    if (idx >= 3 * D * D) return;
    int m = idx / D;
    int k = idx % D;
    WT[(size_t)k * (3 * D) + m] = W[idx];
}

// ---------------- FFMA register-blocked GEMM (proven 36 TF/s) ----------------
// C[N x M] = A[N x 128] @ B[128 x M]; M multiple of 128.
// Tile 128x128, BK=16, 256 threads, 8x8 outputs/thread (2x2 chunks of 4, split 64).
#define BK 16
__global__ __launch_bounds__(256, 2)
void gemm128(const float* __restrict__ A, const float* __restrict__ B,
             float* __restrict__ C, int N, int M) {
    __shared__ float As[BK][132];   // stored transposed As[k][m]
    __shared__ float Bs[BK][128];   // Bs[k][n]

    int tid = threadIdx.x;
    int block_row = blockIdx.y * 128;
    int block_col = blockIdx.x * 128;

    int aRow = tid >> 2;
    int aCol = (tid & 3) * 4;
    int bRow = tid >> 5;
    int bCol = (tid & 31) * 4;
    int tr = (tid >> 4) * 4;
    int tc = (tid & 15) * 4;

    float acc[8][8];
#pragma unroll
    for (int i = 0; i < 8; i++)
#pragma unroll
        for (int j = 0; j < 8; j++) acc[i][j] = 0.0f;

    for (int k0 = 0; k0 < 128; k0 += BK) {
#pragma unroll
        for (int p = 0; p < 2; p++) {
            int r = aRow + p * 64;
            int gr = block_row + r;
            float4 v = make_float4(0.f, 0.f, 0.f, 0.f);
            if (gr < N) v = *(const float4*)(A + (size_t)gr * 128 + k0 + aCol);
            As[aCol + 0][r] = v.x;
            As[aCol + 1][r] = v.y;
            As[aCol + 2][r] = v.z;
            As[aCol + 3][r] = v.w;
        }
#pragma unroll
        for (int p = 0; p < 2; p++) {
            int r = bRow + p * 8;
            float4 v = *(const float4*)(B + (size_t)(k0 + r) * M + block_col + bCol);
            *(float4*)&Bs[r][bCol] = v;
        }
        __syncthreads();

#pragma unroll
        for (int k = 0; k < BK; k++) {
            float4 m0 = *(const float4*)&As[k][tr];
            float4 m1 = *(const float4*)&As[k][tr + 64];
            float4 n0 = *(const float4*)&Bs[k][tc];
            float4 n1 = *(const float4*)&Bs[k][tc + 64];
            float rm[8] = {m0.x, m0.y, m0.z, m0.w, m1.x, m1.y, m1.z, m1.w};
            float rn[8] = {n0.x, n0.y, n0.z, n0.w, n1.x, n1.y, n1.z, n1.w};
#pragma unroll
            for (int i = 0; i < 8; i++)
#pragma unroll
                for (int j = 0; j < 8; j++)
                    acc[i][j] = fmaf(rm[i], rn[j], acc[i][j]);
        }
        __syncthreads();
    }

#pragma unroll
    for (int ii = 0; ii < 2; ii++) {
#pragma unroll
        for (int i = 0; i < 4; i++) {
            int row = block_row + tr + ii * 64 + i;
            if (row >= N) continue;
#pragma unroll
            for (int jj = 0; jj < 2; jj++) {
                int col = block_col + tc + jj * 64;
                float4 r;
                r.x = acc[ii * 4 + i][jj * 4 + 0];
                r.y = acc[ii * 4 + i][jj * 4 + 1];
                r.z = acc[ii * 4 + i][jj * 4 + 2];
                r.w = acc[ii * 4 + i][jj * 4 + 3];
                *(float4*)&C[(size_t)row * M + col] = r;
            }
        }
    }
}

// ---------------- gather: h = embed[node_ids]; also zero agg ----------------
__global__ void gather_kernel(const int* __restrict__ node_ids,
                              const float4* __restrict__ embed4,
                              float4* __restrict__ h4,
                              float4* __restrict__ agg4, int N) {
    int idx = blockIdx.x * blockDim.x + threadIdx.x;
    if (idx >= N * 32) return;
    int n = idx >> 5;
    int c = idx & 31;
    int id = node_ids[n];
    h4[(size_t)n * 32 + c] = embed4[(size_t)id * 32 + c];
    agg4[idx] = make_float4(0.f, 0.f, 0.f, 0.f);
}

// ---------------- edge scatter, 4 edges per warp (MLP=4) ----------------
#define RED4(P, V)                                                         \
    asm volatile("red.global.add.v4.f32 [%0], {%1, %2, %3, %4};"           \
                 :: "l"(P), "f"((V).x), "f"((V).y), "f"((V).z), "f"((V).w) \
                 : "memory")

__global__ void scatter_kernel(const float4* __restrict__ m4,
                               const int* __restrict__ src,
                               const int* __restrict__ dst,
                               float* __restrict__ agg, int E) {
    int w = blockIdx.x * (blockDim.x >> 5) + (threadIdx.x >> 5);
    int lane = threadIdx.x & 31;
    int e0 = w * 4;
    if (e0 >= E) return;
    if (e0 + 4 <= E) {
        int s0 = __ldg(src + e0 + 0), s1 = __ldg(src + e0 + 1);
        int s2 = __ldg(src + e0 + 2), s3 = __ldg(src + e0 + 3);
        int d0 = __ldg(dst + e0 + 0), d1 = __ldg(dst + e0 + 1);
        int d2 = __ldg(dst + e0 + 2), d3 = __ldg(dst + e0 + 3);
        float4 v0 = m4[(size_t)s0 * 32 + lane];
        float4 v1 = m4[(size_t)s1 * 32 + lane];
        float4 v2 = m4[(size_t)s2 * 32 + lane];
        float4 v3 = m4[(size_t)s3 * 32 + lane];
        RED4(agg + (size_t)d0 * D + lane * 4, v0);
        RED4(agg + (size_t)d1 * D + lane * 4, v1);
        RED4(agg + (size_t)d2 * D + lane * 4, v2);
        RED4(agg + (size_t)d3 * D + lane * 4, v3);
    } else {
        for (int e = e0; e < E; e++) {
            int s = __ldg(src + e);
            int d = __ldg(dst + e);
            float4 v = m4[(size_t)s * 32 + lane];
            RED4(agg + (size_t)d * D + lane * 4, v);
        }
    }
}

// ---------------- GRU gate fusion (biases folded); optionally zero agg ----------------
__global__ void gru_kernel(const float4* __restrict__ gi4,
                           const float4* __restrict__ gh4,
                           const float4* __restrict__ bih4,
                           const float4* __restrict__ bhh4,
                           float4* __restrict__ h4,
                           float4* __restrict__ agg4,
                           int total4, int zero_agg) {
    int idx = blockIdx.x * blockDim.x + threadIdx.x;
    if (idx >= total4) return;
    int n = idx >> 5;
    int c = idx & 31;
    const float4* gin = gi4 + (size_t)n * 96;
    const float4* ghn = gh4 + (size_t)n * 96;
    float4 ir = gin[c], iz = gin[c + 32], in_ = gin[c + 64];
    float4 hr = ghn[c], hz = ghn[c + 32], hn = ghn[c + 64];
    float4 bir = bih4[c], biz = bih4[c + 32], bin = bih4[c + 64];
    float4 bhr = bhh4[c], bhz = bhh4[c + 32], bhn = bhh4[c + 64];
    float4 h = h4[idx];
    float4 o;
#define GRU1(X)                                                                 \
    {                                                                           \
        float r = 1.0f / (1.0f + __expf(-(ir.X + bir.X + hr.X + bhr.X)));       \
        float z = 1.0f / (1.0f + __expf(-(iz.X + biz.X + hz.X + bhz.X)));       \
        float nn = tanhf(in_.X + bin.X + r * (hn.X + bhn.X));                   \
        o.X = (1.0f - z) * nn + z * h.X;                                        \
    }
    GRU1(x) GRU1(y) GRU1(z) GRU1(w)
#undef GRU1
    h4[idx] = o;
    if (zero_agg) agg4[idx] = make_float4(0.f, 0.f, 0.f, 0.f);
}

// ---------------- per-graph mean pool (batch sorted) ----------------
__device__ __forceinline__ int lower_bound_dev(const int* a, int n, int key) {
    int lo = 0, hi = n;
    while (lo < hi) {
        int mid = (lo + hi) >> 1;
        if (a[mid] < key) lo = mid + 1; else hi = mid;
    }
    return lo;
}

__global__ void pool_kernel(const float* __restrict__ h,
                            const int* __restrict__ batch,
                            float* __restrict__ out, int N) {
    int g = blockIdx.x;
    int tid = threadIdx.x;
    int sub = tid >> 7;
    int d = tid & 127;
    __shared__ int s_lo, s_hi;
    __shared__ float sbuf[4][128];
    if (tid == 0) {
        s_lo = lower_bound_dev(batch, N, g);
        s_hi = lower_bound_dev(batch, N, g + 1);
    }
    __syncthreads();
    int lo = s_lo, hi = s_hi;
    float acc = 0.0f;
    for (int n = lo + sub; n < hi; n += 4)
        acc += h[(size_t)n * D + d];
    sbuf[sub][d] = acc;
    __syncthreads();
    if (sub == 0) {
        float total = sbuf[0][d] + sbuf[1][d] + sbuf[2][d] + sbuf[3][d];
        float cnt = (float)(hi - lo);
        out[(size_t)g * D + d] = total / fmaxf(cnt, 1.0f);
    }
}

// ---------------- launch ----------------
extern "C" void kernel_launch(void* const* d_in, const int* in_sizes, int n_in,
                              void* d_out, int out_size) {
    const int* node_ids = (const int*)d_in[0];
    const int* edge_index = (const int*)d_in[1];
    const int* batch = (const int*)d_in[2];
    const float* embed = (const float*)d_in[4];
    const float* conv_w = (const float*)d_in[5];   // [2][K][M] — already B layout!
    const float* w_ih = (const float*)d_in[6];
    const float* w_hh = (const float*)d_in[7];
    const float* b_ih = (const float*)d_in[8];
    const float* b_hh = (const float*)d_in[9];
    float* out = (float*)d_out;

    int N = in_sizes[0];
    int E = in_sizes[1] / 2;
    int G = out_size / D;
    const int* src = edge_index;
    const int* dst = edge_index + E;

    float *h, *m, *agg, *gi, *gh, *wihT, *whhT;
    cudaGetSymbolAddress((void**)&h, g_h);
    cudaGetSymbolAddress((void**)&m, g_m);
    cudaGetSymbolAddress((void**)&agg, g_agg);
    cudaGetSymbolAddress((void**)&gi, g_gi);
    cudaGetSymbolAddress((void**)&gh, g_gh);
    cudaGetSymbolAddress((void**)&wihT, g_wihT);
    cudaGetSymbolAddress((void**)&whhT, g_whhT);

    // lazy one-time host-side resources (created on correctness call, before capture)
    static cudaStream_t s2 = nullptr;
    static cudaEvent_t evF[2], evJ[2];
    if (!s2) {
        cudaStreamCreateWithFlags(&s2, cudaStreamNonBlocking);
        for (int i = 0; i < 2; i++) {
            cudaEventCreateWithFlags(&evF[i], cudaEventDisableTiming);
            cudaEventCreateWithFlags(&evJ[i], cudaEventDisableTiming);
        }
    }

    transpose_kernel<<<(3 * D * D + 255) / 256, 256>>>(w_ih, wihT);
    transpose_kernel<<<(3 * D * D + 255) / 256, 256>>>(w_hh, whhT);
    gather_kernel<<<(N * 32 + 255) / 256, 256>>>(node_ids, (const float4*)embed,
                                                 (float4*)h, (float4*)agg, N);

    int rowBlocks = (N + 127) / 128;   // 391

    for (int layer = 0; layer < 2; layer++) {
        // fork: gh = h @ w_hh^T on side stream (independent of m/scatter chain)
        cudaEventRecord(evF[layer], 0);
        cudaStreamWaitEvent(s2, evF[layer], 0);
        gemm128<<<dim3(3, rowBlocks), 256, 0, s2>>>(h, whhT, gh, N, 3 * D);
        cudaEventRecord(evJ[layer], s2);

        // main: m = h @ conv_w[layer]  (conv_w already [K,M])
        gemm128<<<dim3(1, rowBlocks), 256>>>(h, conv_w + (size_t)layer * D * D,
                                             m, N, D);

        // agg[dst] += m[src]  (overlaps gh GEMM on s2)
        {
            int warps = (E + 3) / 4;
            int blocks = (warps + 7) / 8;
            scatter_kernel<<<blocks, 256>>>((const float4*)m, src, dst, agg, E);
        }

        // gi = agg @ w_ih^T
        gemm128<<<dim3(3, rowBlocks), 256>>>(agg, wihT, gi, N, 3 * D);

        // join gh, then fuse gates
        cudaStreamWaitEvent(0, evJ[layer], 0);
        gru_kernel<<<(N * 32 + 255) / 256, 256>>>((const float4*)gi,
                                                  (const float4*)gh,
                                                  (const float4*)b_ih,
                                                  (const float4*)b_hh,
                                                  (float4*)h, (float4*)agg,
                                                  N * 32, layer == 0 ? 1 : 0);
    }

    pool_kernel<<<G, 512>>>(h, batch, out, N);
}